// round 10
// baseline (speedup 1.0000x reference)
#include <cuda_runtime.h>
#include <cuda_bf16.h>
#include <cstdint>
#include <cstddef>

// ---------------------------------------------------------------------------
// LuongAttnDecoderMogLSTM  (B=128, H=1024, S=512, V=32000, MOG=5)
// Round 10: HMMA bf16x3 GEMM with fused split-K reduction + epilogues
// (deterministic last-CTA reduction), interleaved gate tiles with in-kernel
// LSTM, ldmatrix fragment loads, single-sync software pipeline.
// ---------------------------------------------------------------------------

#define Bq 128
#define Hq 1024
#define Sq 512
#define Vq 32000

#define EPI_DIRECT 0
#define EPI_MOG    1
#define EPI_TANH   2
#define EPI_LSTM1  3
#define EPI_LSTM2  4
#define EPI_PLAIN  5

static __device__ float g_x  [Bq*Hq];
static __device__ float g_h  [Bq*Hq];
static __device__ float g_x2 [Bq*Hq];
static __device__ float g_h2 [Bq*Hq];
static __device__ float g_rnn[Bq*Hq];
static __device__ float g_ctx[Bq*Hq];
static __device__ float g_cc [Bq*Hq];
static __device__ float g_part[8*4096*Bq];        // split-K partials (16.8 MB)
static __device__ float g_logits[(size_t)Bq*Vq];  // 16 MB
static __device__ int   g_ctr[64];                // zero-init; reset by reducer

__device__ __forceinline__ float sigf(float x) { return 1.f / (1.f + expf(-x)); }

__device__ __forceinline__ uint32_t smem_u32(const void* p) {
    uint32_t a;
    asm("{ .reg .u64 t; cvta.to.shared.u64 t, %1; cvt.u32.u64 %0, t; }"
        : "=r"(a) : "l"(p));
    return a;
}

#define STS128(addr, a, b, c, d) \
    asm volatile("st.shared.v4.b32 [%0], {%1, %2, %3, %4};" \
                 :: "r"(addr), "r"(a), "r"(b), "r"(c), "r"(d) : "memory")

__device__ __forceinline__ void ldsm4(uint32_t a, uint32_t& r0, uint32_t& r1,
                                      uint32_t& r2, uint32_t& r3) {
    asm volatile("ldmatrix.sync.aligned.m8n8.x4.shared.b16 {%0,%1,%2,%3}, [%4];"
                 : "=r"(r0), "=r"(r1), "=r"(r2), "=r"(r3) : "r"(a));
}

// fp32 -> bf16 hi/lo split (round-to-nearest-even)
__device__ __forceinline__ void split_bf(float f, uint32_t& hb, uint32_t& lb) {
    uint32_t u  = __float_as_uint(f);
    uint32_t hr = (u + 0x7FFFu + ((u >> 16) & 1u)) & 0xFFFF0000u;
    float    lf = f - __uint_as_float(hr);
    uint32_t ul = __float_as_uint(lf);
    uint32_t lr = (ul + 0x7FFFu + ((ul >> 16) & 1u)) & 0xFFFF0000u;
    hb = hr >> 16;  lb = lr >> 16;
}

// Convert 32 fp32 (row r, cols cg..cg+31 of a 128x64 tile) from registers,
// store SW128-swizzled bf16 pairs into hi and lo smem tiles (16 KB each).
__device__ __forceinline__ void cvt_sts8(const float4* f, uint32_t dhi,
                                         uint32_t dlo, int r, int cg)
{
    #pragma unroll
    for (int g = 0; g < 4; g++) {
        float4 f0 = f[2 * g], f1 = f[2 * g + 1];
        uint32_t h[8], l[8];
        split_bf(f0.x, h[0], l[0]); split_bf(f0.y, h[1], l[1]);
        split_bf(f0.z, h[2], l[2]); split_bf(f0.w, h[3], l[3]);
        split_bf(f1.x, h[4], l[4]); split_bf(f1.y, h[5], l[5]);
        split_bf(f1.z, h[6], l[6]); split_bf(f1.w, h[7], l[7]);
        uint32_t p0 = h[0] | (h[1] << 16), p1 = h[2] | (h[3] << 16);
        uint32_t p2 = h[4] | (h[5] << 16), p3 = h[6] | (h[7] << 16);
        uint32_t q0 = l[0] | (l[1] << 16), q1 = l[2] | (l[3] << 16);
        uint32_t q2 = l[4] | (l[5] << 16), q3 = l[6] | (l[7] << 16);
        uint32_t byte = (uint32_t)r * 128u + (uint32_t)(cg + g * 8) * 2u;
        uint32_t sw = byte ^ ((byte >> 3) & 0x70u);
        STS128(dhi + sw, p0, p1, p2, p3);
        STS128(dlo + sw, q0, q1, q2, q3);
    }
}

// Address of a 16B-aligned fragment row in a SW128 128x64-bf16 tile.
__device__ __forceinline__ uint32_t fragaddr(uint32_t base, int row, int bo) {
    return base + (uint32_t)row * 128u
                + (uint32_t)((((bo >> 4) ^ (row & 7)) << 4));
}

#define MMA_BF16(d, a, b0_, b1_) \
    asm volatile("mma.sync.aligned.m16n8k16.row.col.f32.bf16.bf16.f32 " \
        "{%0,%1,%2,%3}, {%4,%5,%6,%7}, {%8,%9}, {%0,%1,%2,%3};" \
        : "+f"((d)[0]), "+f"((d)[1]), "+f"((d)[2]), "+f"((d)[3]) \
        : "r"((a)[0]), "r"((a)[1]), "r"((a)[2]), "r"((a)[3]), \
          "r"(b0_), "r"(b1_))

#define GBUF 65536u
#define SMEM_BYTES (2 * 65536)

// ============================ mma_gemm =====================================
// C[b][n] = sum_k Asel[b][k] * Wsel[rowmap(n)][wc + k]  (M=128, n-tile 128,
// k-chunk 64, bf16x3). Dual input: by >= bySplit uses (A2, W2, wcol0_2).
// interleave: W tile row r -> W row (r>>5)*1024 + bx*32 + (r&31)  (gate tiles)
// epi==EPI_DIRECT: direct row-major write of acc+bias to out1 (stride Nout).
// else: write partial slice `by`, last CTA per tile reduces (fixed order) and
// applies the epilogue. Deterministic.
__global__ void __launch_bounds__(256, 1)
mma_gemm(const float* __restrict__ A,  const float* __restrict__ W,
         int ldw, int wcol0,
         const float* __restrict__ A2, const float* __restrict__ W2,
         int wcol0_2, int bySplit, int klen, int interleave,
         float* __restrict__ Cp, int Np, int target, int epi,
         const float* __restrict__ bias1, const float* __restrict__ bias2,
         const float* __restrict__ aux1,  const float* __restrict__ aux2,
         float* __restrict__ out1, float* __restrict__ out2, int Nout)
{
    extern __shared__ char smem[];
    const uint32_t sb = smem_u32(smem);
    const int tid  = threadIdx.x;
    const int lane = tid & 31;
    const int wid  = tid >> 5;
    const int bx   = blockIdx.x;
    const int by   = blockIdx.y;
    const int T    = klen >> 6;

    // select input set + k offset
    const float* Ause; const float* Wuse; int wc, kb;
    if (by < bySplit) { Ause = A;  Wuse = W;  wc = wcol0;   kb = by * klen; }
    else              { Ause = A2; Wuse = W2; wc = wcol0_2; kb = (by - bySplit) * klen; }

    const int r  = tid >> 1;
    const int cg = (tid & 1) * 32;
    const int wr = interleave ? ((r >> 5) * 1024 + bx * 32 + (r & 31))
                              : (bx * 128 + r);
    const float* Agp = Ause + (size_t)r * 1024 + kb + cg;
    const float* Wgp = Wuse + (size_t)wr * ldw + wc + kb + cg;

    const int wm = (wid & 3) * 32;
    const int wn = (wid >> 2) * 64;
    const int lr = lane & 15;
    const int lk = (lane >> 4) << 4;

    float acc[2][8][4];
    #pragma unroll
    for (int mf = 0; mf < 2; mf++)
        #pragma unroll
        for (int nf = 0; nf < 8; nf++)
            #pragma unroll
            for (int j = 0; j < 4; j++) acc[mf][nf][j] = 0.f;

    float4 fa[8], fw[8];
    #pragma unroll
    for (int i = 0; i < 8; i++) {
        fa[i] = *(const float4*)(Agp + i * 4);
        fw[i] = *(const float4*)(Wgp + i * 4);
    }
    cvt_sts8(fa, sb,           sb + 16384u, r, cg);
    cvt_sts8(fw, sb + 32768u,  sb + 49152u, r, cg);
    if (T > 1) {
        #pragma unroll
        for (int i = 0; i < 8; i++) {
            fa[i] = *(const float4*)(Agp + 64 + i * 4);
            fw[i] = *(const float4*)(Wgp + 64 + i * 4);
        }
    }
    __syncthreads();

    for (int t = 0; t < T; t++) {
        if (t + 1 < T) {   // stage regs (chunk t+1) into the other buffer
            uint32_t bb = sb + (uint32_t)((t + 1) & 1) * GBUF;
            cvt_sts8(fa, bb,          bb + 16384u, r, cg);
            cvt_sts8(fw, bb + 32768u, bb + 49152u, r, cg);
        }
        if (t + 2 < T) {   // prefetch chunk t+2
            #pragma unroll
            for (int i = 0; i < 8; i++) {
                fa[i] = *(const float4*)(Agp + (t + 2) * 64 + i * 4);
                fw[i] = *(const float4*)(Wgp + (t + 2) * 64 + i * 4);
            }
        }
        const uint32_t base = sb + (uint32_t)(t & 1) * GBUF;
        #pragma unroll
        for (int kf = 0; kf < 4; kf++) {
            const int bo = kf * 32 + lk;
            uint32_t ah[2][4], al[2][4];
            #pragma unroll
            for (int mf = 0; mf < 2; mf++) {
                uint32_t ad = fragaddr(base, wm + mf * 16 + lr, bo);
                ldsm4(ad,           ah[mf][0], ah[mf][1], ah[mf][2], ah[mf][3]);
                ldsm4(ad + 16384u,  al[mf][0], al[mf][1], al[mf][2], al[mf][3]);
            }
            #pragma unroll
            for (int p = 0; p < 4; p++) {
                uint32_t bd = fragaddr(base + 32768u, wn + p * 16 + lr, bo);
                uint32_t bh[4], bl[4];
                ldsm4(bd,          bh[0], bh[1], bh[2], bh[3]);
                ldsm4(bd + 16384u, bl[0], bl[1], bl[2], bl[3]);
                #pragma unroll
                for (int q = 0; q < 2; q++) {
                    const int nf = 2 * p + q;
                    #pragma unroll
                    for (int mf = 0; mf < 2; mf++) {
                        MMA_BF16(acc[mf][nf], ah[mf], bh[q], bh[q + 2]);
                        MMA_BF16(acc[mf][nf], al[mf], bh[q], bh[q + 2]);
                        MMA_BF16(acc[mf][nf], ah[mf], bl[q], bl[q + 2]);
                    }
                }
            }
        }
        __syncthreads();
    }

    // ----------------- epilogue -----------------
    if (epi == EPI_DIRECT) {
        #pragma unroll
        for (int mf = 0; mf < 2; mf++) {
            int r0 = wm + mf * 16 + (lane >> 2);
            #pragma unroll
            for (int nf = 0; nf < 8; nf++) {
                int n = bx * 128 + wn + nf * 8 + (lane & 3) * 2;
                float b0 = bias1[n], b1 = bias1[n + 1];
                *(float2*)&out1[(size_t)r0 * Nout + n] =
                    make_float2(acc[mf][nf][0] + b0, acc[mf][nf][1] + b1);
                *(float2*)&out1[(size_t)(r0 + 8) * Nout + n] =
                    make_float2(acc[mf][nf][2] + b0, acc[mf][nf][3] + b1);
            }
        }
        return;
    }

    // partial write: [slice by][b][bx*128 + local]
    {
        float* o = Cp + (size_t)by * Np * 128;
        #pragma unroll
        for (int mf = 0; mf < 2; mf++) {
            int r0 = wm + mf * 16 + (lane >> 2);
            #pragma unroll
            for (int nf = 0; nf < 8; nf++) {
                int n = bx * 128 + wn + nf * 8 + (lane & 3) * 2;
                *(float2*)&o[(size_t)r0 * Np + n] =
                    make_float2(acc[mf][nf][0], acc[mf][nf][1]);
                *(float2*)&o[(size_t)(r0 + 8) * Np + n] =
                    make_float2(acc[mf][nf][2], acc[mf][nf][3]);
            }
        }
    }

    __threadfence();
    __syncthreads();
    __shared__ int s_old;
    if (tid == 0) {
        s_old = atomicAdd(&g_ctr[bx], 1);
        __threadfence();
    }
    __syncthreads();
    if (s_old != target - 1) return;

    // -------- last CTA: deterministic reduction + fused epilogue --------
    if (epi == EPI_LSTM1 || epi == EPI_LSTM2) {
        for (int e = 0; e < 16; e++) {
            int oid = e * 256 + tid;          // 128 b x 32 hh
            int b  = oid >> 5;
            int hh = oid & 31;
            int hg = bx * 32 + hh;
            float v0 = 0.f, v1 = 0.f, v2 = 0.f, v3 = 0.f;
            for (int s = 0; s < target; s++) {
                const float* p = Cp + (size_t)s * Np * 128
                                    + (size_t)b * Np + bx * 128 + hh;
                v0 += p[0]; v1 += p[32]; v2 += p[64]; v3 += p[96];
            }
            float vi = v0 + bias1[hg]          + bias2[hg];
            float vf = v1 + bias1[1024 + hg]   + bias2[1024 + hg];
            float vg = v2 + bias1[2048 + hg]   + bias2[2048 + hg];
            float vo = v3 + bias1[3072 + hg]   + bias2[3072 + hg];
            float c = sigf(vi) * tanhf(vg);
            if (epi == EPI_LSTM1) c += sigf(vf) * aux1[(size_t)b * 1024 + hg];
            float hv = sigf(vo) * tanhf(c);
            if (out1) out1[(size_t)b * 1024 + hg] = hv;
            if (out2) {
                float f = 8.f * sigf(aux2[hg]) * sigf(aux2[2048 + hg])
                              * sigf(aux2[4096 + hg]);
                out2[(size_t)b * 1024 + hg] = hv * f;
            }
        }
    } else {
        for (int e = 0; e < 64; e++) {
            int oid = e * 256 + tid;          // 128 b x 128 nl
            int b  = oid >> 7;
            int nl = oid & 127;
            int ng = bx * 128 + nl;
            float v = 0.f;
            for (int s = 0; s < target; s++)
                v += Cp[(size_t)s * Np * 128 + (size_t)b * Np + ng];
            v += bias1[ng];
            size_t oi = (size_t)b * Nout + ng;
            if (epi == EPI_MOG)       out1[oi] *= 2.f * sigf(v);
            else if (epi == EPI_TANH) out1[oi]  = tanhf(v);
            else                      out1[oi]  = v;
        }
    }
    if (tid == 0) g_ctr[bx] = 0;   // reset for next launch / replay
}

// ======================= prep: state copy + embedding ======================
__global__ void prep_kernel(const int* __restrict__ step,
                            const float* __restrict__ emb,
                            const float* __restrict__ h1,
                            float* __restrict__ x, float* __restrict__ h)
{
    int idx = blockIdx.x * blockDim.x + threadIdx.x;
    if (idx >= Bq * Hq) return;
    h[idx] = h1[idx];
    int b = idx >> 10, hh = idx & 1023;
    x[idx] = emb[(size_t)step[b] * Hq + hh];
}

// ================= fused attention (online softmax, prefetch) ==============
__global__ void __launch_bounds__(256)
attention_kernel(const float* __restrict__ rnn,   // [B][H]
                 const float* __restrict__ enc,   // [S][B][H]
                 float* __restrict__ ctx)         // [B][H]
{
    int b    = blockIdx.x;
    int tid  = threadIdx.x;
    int w    = tid >> 5;
    int lane = tid & 31;

    const float4* rb = (const float4*)(rnn + (size_t)b * Hq);
    float4 q[8];
    #pragma unroll
    for (int i = 0; i < 8; i++) q[i] = rb[i * 32 + lane];

    float m = -1e30f, l = 0.f;
    float4 acc[8];
    #pragma unroll
    for (int i = 0; i < 8; i++) acc[i] = make_float4(0.f, 0.f, 0.f, 0.f);

    float4 ev[8], evn[8];
    {
        const float4* e = (const float4*)(enc + ((size_t)w * Bq + b) * Hq);
        #pragma unroll
        for (int i = 0; i < 8; i++) ev[i] = e[i * 32 + lane];
    }

    for (int s = w; s < Sq; s += 8) {
        int sn = s + 8;
        if (sn < Sq) {
            const float4* e = (const float4*)(enc + ((size_t)sn * Bq + b) * Hq);
            #pragma unroll
            for (int i = 0; i < 8; i++) evn[i] = e[i * 32 + lane];
        }
        float dot = 0.f;
        #pragma unroll
        for (int i = 0; i < 8; i++)
            dot += q[i].x * ev[i].x + q[i].y * ev[i].y
                 + q[i].z * ev[i].z + q[i].w * ev[i].w;
        #pragma unroll
        for (int o = 16; o > 0; o >>= 1) dot += __shfl_xor_sync(0xffffffffu, dot, o);
        float mn   = fmaxf(m, dot);
        float corr = expf(m - mn);
        float p    = expf(dot - mn);
        l = l * corr + p;
        #pragma unroll
        for (int i = 0; i < 8; i++) {
            acc[i].x = acc[i].x * corr + p * ev[i].x;
            acc[i].y = acc[i].y * corr + p * ev[i].y;
            acc[i].z = acc[i].z * corr + p * ev[i].z;
            acc[i].w = acc[i].w * corr + p * ev[i].w;
        }
        m = mn;
        #pragma unroll
        for (int i = 0; i < 8; i++) ev[i] = evn[i];
    }

    __shared__ float sm[8], sl[8];
    __shared__ float sacc[8][Hq];
    #pragma unroll
    for (int i = 0; i < 8; i++) ((float4*)sacc[w])[i * 32 + lane] = acc[i];
    if (lane == 0) { sm[w] = m; sl[w] = l; }
    __syncthreads();

    float M = -1e30f;
    #pragma unroll
    for (int ww = 0; ww < 8; ww++) M = fmaxf(M, sm[ww]);
    float wexp[8], L = 0.f;
    #pragma unroll
    for (int ww = 0; ww < 8; ww++) { wexp[ww] = expf(sm[ww] - M); L += sl[ww] * wexp[ww]; }
    float invL = 1.f / L;

    for (int hh = tid; hh < Hq; hh += 256) {
        float v = 0.f;
        #pragma unroll
        for (int ww = 0; ww < 8; ww++) v += sacc[ww][hh] * wexp[ww];
        ctx[(size_t)b * Hq + hh] = v * invL;
    }
}

// ================= online row softmax + hidden copy ========================
__global__ void softmax_kernel(const float* __restrict__ logits,
                               float* __restrict__ out,
                               const float* __restrict__ h2, int copy_hidden)
{
    int b = blockIdx.x, tid = threadIdx.x;
    const float4* row = (const float4*)(logits + (size_t)b * Vq);

    float m = -1e30f, l = 0.f;
    for (int v = tid; v < Vq / 4; v += 256) {
        float4 x = row[v];
        float mx = fmaxf(fmaxf(x.x, x.y), fmaxf(x.z, x.w));
        float mn = fmaxf(m, mx);
        l = l * expf(m - mn) + expf(x.x - mn) + expf(x.y - mn)
                             + expf(x.z - mn) + expf(x.w - mn);
        m = mn;
    }
    __shared__ float sm[256], sl[256];
    sm[tid] = m; sl[tid] = l; __syncthreads();
    for (int st = 128; st > 0; st >>= 1) {
        if (tid < st) {
            float m2 = fmaxf(sm[tid], sm[tid + st]);
            sl[tid] = sl[tid] * expf(sm[tid] - m2)
                    + sl[tid + st] * expf(sm[tid + st] - m2);
            sm[tid] = m2;
        }
        __syncthreads();
    }
    float M = sm[0], inv = 1.f / sl[0];

    float4* o = (float4*)(out + (size_t)b * Vq);
    for (int v = tid; v < Vq / 4; v += 256) {
        float4 x = row[v];
        o[v] = make_float4(expf(x.x - M) * inv, expf(x.y - M) * inv,
                           expf(x.z - M) * inv, expf(x.w - M) * inv);
    }
    if (copy_hidden) {
        const float* hh = h2 + (size_t)b * Hq;
        float* od = out + (size_t)Bq * Vq + (size_t)b * Hq;
        for (int j = tid; j < Hq; j += 256) od[j] = hh[j];
    }
}

// ------------------------------- launch ------------------------------------
extern "C" void kernel_launch(void* const* d_in, const int* in_sizes, int n_in,
                              void* d_out, int out_size)
{
    const int*   step  = (const int*)  d_in[0];
    const float* enc   = (const float*)d_in[1];
    const float* h1    = (const float*)d_in[2];
    const float* c1    = (const float*)d_in[3];
    const float* emb   = (const float*)d_in[4];
    const float* mog1W = (const float*)d_in[5];
    const float* mog1b = (const float*)d_in[6];
    const float* Wih1  = (const float*)d_in[7];
    const float* Whh1  = (const float*)d_in[8];
    const float* bih1  = (const float*)d_in[9];
    const float* bhh1  = (const float*)d_in[10];
    const float* mog2b = (const float*)d_in[12];
    const float* Wih2  = (const float*)d_in[13];
    const float* bih2  = (const float*)d_in[15];
    const float* bhh2  = (const float*)d_in[16];
    const float* fcW   = (const float*)d_in[17];
    const float* fcb   = (const float*)d_in[18];
    const float* ccW   = (const float*)d_in[19];
    const float* ccb   = (const float*)d_in[20];
    const float* outW  = (const float*)d_in[21];
    const float* outb  = (const float*)d_in[22];
    float* out = (float*)d_out;

    float *x, *h, *x2, *h2, *rnn, *ctx, *cc, *part, *logits;
    cudaGetSymbolAddress((void**)&x,     g_x);
    cudaGetSymbolAddress((void**)&h,     g_h);
    cudaGetSymbolAddress((void**)&x2,    g_x2);
    cudaGetSymbolAddress((void**)&h2,    g_h2);
    cudaGetSymbolAddress((void**)&rnn,   g_rnn);
    cudaGetSymbolAddress((void**)&ctx,   g_ctx);
    cudaGetSymbolAddress((void**)&cc,    g_cc);
    cudaGetSymbolAddress((void**)&part,  g_part);
    cudaGetSymbolAddress((void**)&logits,g_logits);

    cudaFuncSetAttribute(mma_gemm, cudaFuncAttributeMaxDynamicSharedMemorySize,
                         SMEM_BYTES);

    prep_kernel<<<(Bq*Hq)/256, 256>>>(step, emb, h1, x, h);

    // layer-1 mogrifier: 5 dependent GEMMs, fused mog epilogue (KS=16)
    for (int i = 0; i < 5; i++) {
        const float* src = (i % 2 == 0) ? h : x;
        float*       tgt = (i % 2 == 0) ? x : h;
        mma_gemm<<<dim3(8, 16), 256, SMEM_BYTES>>>(
            src, mog1W + (size_t)i * Hq * Hq, Hq, 0,
            nullptr, nullptr, 0, 16, 64, 0,
            part, Hq, 16, EPI_MOG,
            mog1b + i * Hq, nullptr, nullptr, nullptr, tgt, nullptr, Hq);
    }

    // layer-1 gates: x@Wih1 + h@Whh1 in one dual-input launch (4+4 slices),
    // interleaved gate tiles; reducer = LSTM cell + layer-2 mog scale -> x2
    mma_gemm<<<dim3(32, 8), 256, SMEM_BYTES>>>(
        x, Wih1, Hq, 0, h, Whh1, 0, 4, 256, 1,
        part, 4*Hq, 8, EPI_LSTM1,
        bih1, bhh1, c1, mog2b, nullptr, x2, Hq);

    // layer-2 gates: x2@Wih2; reducer = LSTM (c_prev=0) -> h2
    mma_gemm<<<dim3(32, 4), 256, SMEM_BYTES>>>(
        x2, Wih2, Hq, 0, nullptr, nullptr, 0, 4, 256, 1,
        part, 4*Hq, 4, EPI_LSTM2,
        bih2, bhh2, nullptr, nullptr, h2, nullptr, Hq);

    // fc: h2@fcW^T + fcb -> rnn (KS=16, plain reducer)
    mma_gemm<<<dim3(8, 16), 256, SMEM_BYTES>>>(
        h2, fcW, Hq, 0, nullptr, nullptr, 0, 16, 64, 0,
        part, Hq, 16, EPI_PLAIN,
        fcb, nullptr, nullptr, nullptr, rnn, nullptr, Hq);

    // fused Luong attention (single pass over enc)
    attention_kernel<<<Bq, 256>>>(rnn, enc, ctx);

    // concat: [rnn|ctx]@ccW^T in one dual-input launch (8+8 slices), tanh
    mma_gemm<<<dim3(8, 16), 256, SMEM_BYTES>>>(
        rnn, ccW, 2*Hq, 0, ctx, ccW, Hq, 8, 128, 0,
        part, Hq, 16, EPI_TANH,
        ccb, nullptr, nullptr, nullptr, cc, nullptr, Hq);

    // output projection: direct write logits (+bias)
    mma_gemm<<<dim3(Vq/128, 1), 256, SMEM_BYTES>>>(
        cc, outW, Hq, 0, nullptr, nullptr, 0, 1, 1024, 0,
        nullptr, 0, 0, EPI_DIRECT,
        outb, nullptr, nullptr, nullptr, logits, nullptr, Vq);

    // softmax + hidden copy
    int copy_hidden = (out_size >= Bq*Vq + Bq*Hq) ? 1 : 0;
    softmax_kernel<<<Bq, 256>>>(logits, out, h2, copy_hidden);
}

// round 11
// speedup vs baseline: 2.4432x; 2.4432x over previous
#include <cuda_runtime.h>
#include <cuda_bf16.h>
#include <cstdint>
#include <cstddef>

// ---------------------------------------------------------------------------
// LuongAttnDecoderMogLSTM  (B=128, H=1024, S=512, V=32000, MOG=5)
// Round 11: ONE persistent kernel for the whole network. Grid-wide barriers,
// HMMA bf16x3 GEMM phases (pre-split activations, cheap PRMT/bf16x2 weight
// split), grid-parallel fused epilogues, flash attention + softmax phases.
// ---------------------------------------------------------------------------

#define Bq 128
#define Hq 1024
#define Sq 512
#define Vq 32000
#define NB 128          // persistent grid size (1 CTA/SM, all resident)

// activations: fp32 where re-read by epilogues/attention, bf16 hi/lo for GEMMs
static __device__ float    g_x  [Bq*Hq];
static __device__ uint16_t g_xh [Bq*Hq], g_xl [Bq*Hq];
static __device__ float    g_h  [Bq*Hq];
static __device__ uint16_t g_hh [Bq*Hq], g_hl [Bq*Hq];
static __device__ uint16_t g_x2h[Bq*Hq], g_x2l[Bq*Hq];
static __device__ float    g_h2 [Bq*Hq];
static __device__ uint16_t g_h2h[Bq*Hq], g_h2l[Bq*Hq];
static __device__ float    g_rnn[Bq*Hq];
static __device__ uint16_t g_rnh[Bq*Hq], g_rnl[Bq*Hq];
static __device__ uint16_t g_cxh[Bq*Hq], g_cxl[Bq*Hq];
static __device__ uint16_t g_cch[Bq*Hq], g_ccl[Bq*Hq];
static __device__ float    g_part[8*4096*Bq];        // split-K partials
static __device__ float    g_logits[(size_t)Bq*Vq];
static __device__ int      g_barc, g_barg;           // grid barrier state

__device__ __forceinline__ float sigf(float x) { return 1.f / (1.f + expf(-x)); }

__device__ __forceinline__ uint32_t smem_u32(const void* p) {
    uint32_t a;
    asm("{ .reg .u64 t; cvta.to.shared.u64 t, %1; cvt.u32.u64 %0, t; }"
        : "=r"(a) : "l"(p));
    return a;
}

// L1-bypassing loads (persistent kernel: no per-launch L1D flush, and these
// buffers are written by other SMs between phases)
__device__ __forceinline__ float4 ldcg4(const float* p) {
    float4 v;
    asm volatile("ld.global.cg.v4.f32 {%0,%1,%2,%3}, [%4];"
                 : "=f"(v.x), "=f"(v.y), "=f"(v.z), "=f"(v.w) : "l"(p));
    return v;
}
__device__ __forceinline__ uint4 ldcg4u(const void* p) {
    uint4 v;
    asm volatile("ld.global.cg.v4.b32 {%0,%1,%2,%3}, [%4];"
                 : "=r"(v.x), "=r"(v.y), "=r"(v.z), "=r"(v.w) : "l"(p));
    return v;
}

// grid-wide barrier: sense via monotonically increasing generation counter.
// All NB CTAs are co-resident (1 CTA/SM, NB <= 148) so spinning is safe.
__device__ __forceinline__ void gridbar() {
    __syncthreads();
    if (threadIdx.x == 0) {
        __threadfence();
        int gen = *(volatile int*)&g_barg;
        if (atomicAdd(&g_barc, 1) == NB - 1) {
            g_barc = 0;
            __threadfence();
            *(volatile int*)&g_barg = gen + 1;
        } else {
            while (*(volatile int*)&g_barg == gen) { }
        }
        __threadfence();
    }
    __syncthreads();
}

#define STS128(addr, a, b, c, d) \
    asm volatile("st.shared.v4.b32 [%0], {%1, %2, %3, %4};" \
                 :: "r"(addr), "r"(a), "r"(b), "r"(c), "r"(d) : "memory")

__device__ __forceinline__ void ldsm4(uint32_t a, uint32_t& r0, uint32_t& r1,
                                      uint32_t& r2, uint32_t& r3) {
    asm volatile("ldmatrix.sync.aligned.m8n8.x4.shared.b16 {%0,%1,%2,%3}, [%4];"
                 : "=r"(r0), "=r"(r1), "=r"(r2), "=r"(r3) : "r"(a));
}

// cheap fp32 -> (bf16 hi truncated, bf16 lo rounded) for a pair of floats.
// hi = top 16 bits (exact truncation), lo = rn_bf16(f - hi). Dropped lo*lo
// term in the 3-MMA product is ~2^-16 relative.
__device__ __forceinline__ void cvt_pair(float f0, float f1,
                                         uint32_t& hp, uint32_t& lp) {
    uint32_t u0 = __float_as_uint(f0), u1 = __float_as_uint(f1);
    asm("prmt.b32 %0, %1, %2, 0x7632;" : "=r"(hp) : "r"(u0), "r"(u1));
    float l0 = f0 - __uint_as_float(u0 & 0xFFFF0000u);
    float l1 = f1 - __uint_as_float(u1 & 0xFFFF0000u);
    asm("cvt.rn.bf16x2.f32 %0, %1, %2;" : "=r"(lp) : "f"(l1), "f"(l0));
}

// store 4 consecutive activation values as fp32-splits (o must be 4-aligned)
__device__ __forceinline__ void store_split(uint16_t* th, uint16_t* tl,
                                            size_t o, float a, float b,
                                            float c, float d) {
    uint32_t h0, h1, l0, l1;
    cvt_pair(a, b, h0, l0);
    cvt_pair(c, d, h1, l1);
    *(uint2*)&th[o] = make_uint2(h0, h1);
    *(uint2*)&tl[o] = make_uint2(l0, l1);
}

// 16B-aligned fragment row address in a SW128 128x64-bf16 smem tile
__device__ __forceinline__ uint32_t fragaddr(uint32_t base, int row, int bo) {
    return base + (uint32_t)row * 128u
                + (uint32_t)((((bo >> 4) ^ (row & 7)) << 4));
}

#define MMA_BF16(d, a, b0_, b1_) \
    asm volatile("mma.sync.aligned.m16n8k16.row.col.f32.bf16.bf16.f32 " \
        "{%0,%1,%2,%3}, {%4,%5,%6,%7}, {%8,%9}, {%0,%1,%2,%3};" \
        : "+f"((d)[0]), "+f"((d)[1]), "+f"((d)[2]), "+f"((d)[3]) \
        : "r"((a)[0]), "r"((a)[1]), "r"((a)[2]), "r"((a)[3]), \
          "r"(b0_), "r"(b1_))

#define GBUF 65536u
#define SMEM_BYTES 131072

// ============================ gemm_tile ====================================
// One 128(b) x 128(n) x (64*T)(k) tile job, bf16x3.
// A comes pre-split (Ah/Al bf16 [128][1024], k offset akoff).
// W fp32 row-major [*][ldw]: rows wrow0.., cols wkoff.. ; split in-kernel.
// Dout!=0: direct row-major write acc+bias at cols n0.. (stride Nd).
// else: partial write into Pout (= slice base) at [b][PNp], cols n0..
__device__ __noinline__ void gemm_tile(uint32_t sb,
    const uint16_t* __restrict__ Ah, const uint16_t* __restrict__ Al, int akoff,
    const float* __restrict__ W, int ldw, int wrow0, int wkoff, int T,
    float* __restrict__ Pout, int PNp, int n0,
    const float* __restrict__ bias, float* __restrict__ Dout, int Nd)
{
    const int tid = threadIdx.x, lane = tid & 31, wid = tid >> 5;
    const int r = tid >> 1, cg = (tid & 1) * 32;
    const uint16_t* ahp = Ah + (size_t)r * Hq + akoff + cg;
    const uint16_t* alp = Al + (size_t)r * Hq + akoff + cg;
    const float*    wp  = W  + (size_t)(wrow0 + r) * ldw + wkoff + cg;

    const int wm = (wid & 3) * 32, wn = (wid >> 2) * 64;
    const int lr = lane & 15, lk = (lane >> 4) << 4;

    float acc[2][8][4];
    #pragma unroll
    for (int mf = 0; mf < 2; mf++)
        #pragma unroll
        for (int nf = 0; nf < 8; nf++)
            #pragma unroll
            for (int j = 0; j < 4; j++) acc[mf][nf][j] = 0.f;

    uint4 pa[4], pb[4]; float4 fw[8];
    #pragma unroll
    for (int g = 0; g < 4; g++) {
        pa[g] = ldcg4u(ahp + g * 8);
        pb[g] = ldcg4u(alp + g * 8);
    }
    #pragma unroll
    for (int i = 0; i < 8; i++) fw[i] = *(const float4*)(wp + i * 4);

    for (int t = 0; t < T; t++) {
        const uint32_t base = sb + (uint32_t)(t & 1) * GBUF;
        #pragma unroll
        for (int g = 0; g < 4; g++) {
            uint32_t byte = (uint32_t)r * 128u + (uint32_t)(cg + g * 8) * 2u;
            uint32_t sw = byte ^ ((byte >> 3) & 0x70u);
            STS128(base + sw,           pa[g].x, pa[g].y, pa[g].z, pa[g].w);
            STS128(base + 16384u + sw,  pb[g].x, pb[g].y, pb[g].z, pb[g].w);
        }
        #pragma unroll
        for (int g = 0; g < 4; g++) {
            float4 f0 = fw[2 * g], f1 = fw[2 * g + 1];
            uint32_t h0, h1, h2, h3, l0, l1, l2, l3;
            cvt_pair(f0.x, f0.y, h0, l0); cvt_pair(f0.z, f0.w, h1, l1);
            cvt_pair(f1.x, f1.y, h2, l2); cvt_pair(f1.z, f1.w, h3, l3);
            uint32_t byte = (uint32_t)r * 128u + (uint32_t)(cg + g * 8) * 2u;
            uint32_t sw = byte ^ ((byte >> 3) & 0x70u);
            STS128(base + 32768u + sw, h0, h1, h2, h3);
            STS128(base + 49152u + sw, l0, l1, l2, l3);
        }
        __syncthreads();

        if (t + 1 < T) {
            #pragma unroll
            for (int g = 0; g < 4; g++) {
                pa[g] = ldcg4u(ahp + (t + 1) * 64 + g * 8);
                pb[g] = ldcg4u(alp + (t + 1) * 64 + g * 8);
            }
            #pragma unroll
            for (int i = 0; i < 8; i++)
                fw[i] = *(const float4*)(wp + (t + 1) * 64 + i * 4);
        }

        #pragma unroll
        for (int kf = 0; kf < 4; kf++) {
            const int bo = kf * 32 + lk;
            uint32_t ah4[2][4], al4[2][4];
            #pragma unroll
            for (int mf = 0; mf < 2; mf++) {
                uint32_t ad = fragaddr(base, wm + mf * 16 + lr, bo);
                ldsm4(ad,          ah4[mf][0], ah4[mf][1], ah4[mf][2], ah4[mf][3]);
                ldsm4(ad + 16384u, al4[mf][0], al4[mf][1], al4[mf][2], al4[mf][3]);
            }
            #pragma unroll
            for (int p = 0; p < 4; p++) {
                uint32_t bd = fragaddr(base + 32768u, wn + p * 16 + lr, bo);
                uint32_t bh[4], bl[4];
                ldsm4(bd,          bh[0], bh[1], bh[2], bh[3]);
                ldsm4(bd + 16384u, bl[0], bl[1], bl[2], bl[3]);
                #pragma unroll
                for (int q = 0; q < 2; q++) {
                    const int nf = 2 * p + q;
                    #pragma unroll
                    for (int mf = 0; mf < 2; mf++) {
                        MMA_BF16(acc[mf][nf], ah4[mf], bh[q], bh[q + 2]);
                        MMA_BF16(acc[mf][nf], al4[mf], bh[q], bh[q + 2]);
                        MMA_BF16(acc[mf][nf], ah4[mf], bl[q], bl[q + 2]);
                    }
                }
            }
        }
        __syncthreads();
    }

    if (Dout) {
        #pragma unroll
        for (int mf = 0; mf < 2; mf++) {
            int rr = wm + mf * 16 + (lane >> 2);
            #pragma unroll
            for (int nf = 0; nf < 8; nf++) {
                int nn = n0 + wn + nf * 8 + (lane & 3) * 2;
                float b0 = bias[nn], b1 = bias[nn + 1];
                *(float2*)&Dout[(size_t)rr * Nd + nn] =
                    make_float2(acc[mf][nf][0] + b0, acc[mf][nf][1] + b1);
                *(float2*)&Dout[(size_t)(rr + 8) * Nd + nn] =
                    make_float2(acc[mf][nf][2] + b0, acc[mf][nf][3] + b1);
            }
        }
    } else {
        #pragma unroll
        for (int mf = 0; mf < 2; mf++) {
            int rr = wm + mf * 16 + (lane >> 2);
            #pragma unroll
            for (int nf = 0; nf < 8; nf++) {
                int nn = n0 + wn + nf * 8 + (lane & 3) * 2;
                *(float2*)&Pout[(size_t)rr * PNp + nn] =
                    make_float2(acc[mf][nf][0], acc[mf][nf][1]);
                *(float2*)&Pout[(size_t)(rr + 8) * PNp + nn] =
                    make_float2(acc[mf][nf][2], acc[mf][nf][3]);
            }
        }
    }
}

// ============================ mega kernel ==================================
__global__ void __launch_bounds__(256, 1)
mega(const int* __restrict__ step, const float* __restrict__ enc,
     const float* __restrict__ h1, const float* __restrict__ c1,
     const float* __restrict__ emb,
     const float* __restrict__ mog1W, const float* __restrict__ mog1b,
     const float* __restrict__ Wih1, const float* __restrict__ Whh1,
     const float* __restrict__ bih1, const float* __restrict__ bhh1,
     const float* __restrict__ mog2b, const float* __restrict__ Wih2,
     const float* __restrict__ bih2, const float* __restrict__ bhh2,
     const float* __restrict__ fcW, const float* __restrict__ fcb,
     const float* __restrict__ ccW, const float* __restrict__ ccb,
     const float* __restrict__ outW, const float* __restrict__ outb,
     float* __restrict__ out, int copy_hidden)
{
    extern __shared__ char smem[];
    const uint32_t sb = smem_u32(smem);
    const int cta = blockIdx.x, tid = threadIdx.x;
    const int gid = cta * 256 + tid;       // 0..32767
    const int eb  = gid >> 8;              // batch for elementwise phases
    const int ec  = (gid & 255) * 4;       // 4 consecutive cols

    // ---- P0: prep (embed + state copy, with splits) ----
    {
        int s = step[eb];
        float4 xv = *(const float4*)(emb + (size_t)s * Hq + ec);
        float4 hv = *(const float4*)(h1 + (size_t)eb * Hq + ec);
        size_t o = (size_t)eb * Hq + ec;
        *(float4*)&g_x[o] = xv;
        *(float4*)&g_h[o] = hv;
        store_split(g_xh, g_xl, o, xv.x, xv.y, xv.z, xv.w);
        store_split(g_hh, g_hl, o, hv.x, hv.y, hv.z, hv.w);
    }
    gridbar();

    // ---- P1-P5: layer-1 mogrifier (i even: g(h) scales x; odd: g(x) scales h)
    #pragma unroll 1
    for (int i = 0; i < 5; i++) {
        const uint16_t* Ah = (i & 1) ? g_xh : g_hh;
        const uint16_t* Al = (i & 1) ? g_xl : g_hl;
        int bx = cta >> 4, ks = cta & 15;
        gemm_tile(sb, Ah, Al, ks * 64, mog1W + (size_t)i * Hq * Hq, Hq,
                  bx * 128, ks * 64, 1,
                  g_part + (size_t)ks * Hq * 128, Hq, bx * 128,
                  nullptr, nullptr, 0);
        gridbar();
        {
            float v0 = 0.f, v1 = 0.f, v2 = 0.f, v3 = 0.f;
            for (int s2 = 0; s2 < 16; s2++) {
                float4 p = ldcg4(g_part + (size_t)s2 * Hq * 128
                                        + (size_t)eb * Hq + ec);
                v0 += p.x; v1 += p.y; v2 += p.z; v3 += p.w;
            }
            float4 bv = *(const float4*)(mog1b + i * Hq + ec);
            float*    tf = (i & 1) ? g_h  : g_x;
            uint16_t* th = (i & 1) ? g_hh : g_xh;
            uint16_t* tl = (i & 1) ? g_hl : g_xl;
            size_t o = (size_t)eb * Hq + ec;
            float4 xo = ldcg4(tf + o);
            float n0 = xo.x * 2.f * sigf(v0 + bv.x);
            float n1 = xo.y * 2.f * sigf(v1 + bv.y);
            float n2 = xo.z * 2.f * sigf(v2 + bv.z);
            float n3 = xo.w * 2.f * sigf(v3 + bv.w);
            *(float4*)&tf[o] = make_float4(n0, n1, n2, n3);
            store_split(th, tl, o, n0, n1, n2, n3);
        }
        gridbar();
    }

    // ---- P6: layer-1 gates (x@Wih1 + h@Whh1), 2 jobs/CTA ----
    {
        int bx = cta >> 2, ks = cta & 3;
        gemm_tile(sb, g_xh, g_xl, ks * 256, Wih1, Hq, bx * 128, ks * 256, 4,
                  g_part + (size_t)ks * 4096 * 128, 4096, bx * 128,
                  nullptr, nullptr, 0);
        gemm_tile(sb, g_hh, g_hl, ks * 256, Whh1, Hq, bx * 128, ks * 256, 4,
                  g_part + (size_t)(4 + ks) * 4096 * 128, 4096, bx * 128,
                  nullptr, nullptr, 0);
    }
    gridbar();
    {   // LSTM1 + layer-2 mogrifier (bias-only; h2=0 exactly) -> x2 splits
        float vi[4] = {0,0,0,0}, vf[4] = {0,0,0,0};
        float vg[4] = {0,0,0,0}, vo[4] = {0,0,0,0};
        for (int s2 = 0; s2 < 8; s2++) {
            const float* pb = g_part + (size_t)s2 * 4096 * 128
                                     + (size_t)eb * 4096;
            float4 a = ldcg4(pb + ec);
            float4 b = ldcg4(pb + 1024 + ec);
            float4 c = ldcg4(pb + 2048 + ec);
            float4 d = ldcg4(pb + 3072 + ec);
            vi[0]+=a.x; vi[1]+=a.y; vi[2]+=a.z; vi[3]+=a.w;
            vf[0]+=b.x; vf[1]+=b.y; vf[2]+=b.z; vf[3]+=b.w;
            vg[0]+=c.x; vg[1]+=c.y; vg[2]+=c.z; vg[3]+=c.w;
            vo[0]+=d.x; vo[1]+=d.y; vo[2]+=d.z; vo[3]+=d.w;
        }
        float4 cv = *(const float4*)(c1 + (size_t)eb * Hq + ec);
        float cvv[4] = {cv.x, cv.y, cv.z, cv.w};
        float x2v[4];
        #pragma unroll
        for (int j = 0; j < 4; j++) {
            int hg = ec + j;
            float i_ = vi[j] + bih1[hg]        + bhh1[hg];
            float f_ = vf[j] + bih1[1024 + hg] + bhh1[1024 + hg];
            float g_ = vg[j] + bih1[2048 + hg] + bhh1[2048 + hg];
            float o_ = vo[j] + bih1[3072 + hg] + bhh1[3072 + hg];
            float c  = sigf(f_) * cvv[j] + sigf(i_) * tanhf(g_);
            float hv = sigf(o_) * tanhf(c);
            float sc = 8.f * sigf(mog2b[hg]) * sigf(mog2b[2048 + hg])
                           * sigf(mog2b[4096 + hg]);
            x2v[j] = hv * sc;
        }
        store_split(g_x2h, g_x2l, (size_t)eb * Hq + ec,
                    x2v[0], x2v[1], x2v[2], x2v[3]);
    }
    gridbar();

    // ---- P7: layer-2 gates (x2@Wih2) ----
    {
        int bx = cta >> 2, ks = cta & 3;
        gemm_tile(sb, g_x2h, g_x2l, ks * 256, Wih2, Hq, bx * 128, ks * 256, 4,
                  g_part + (size_t)ks * 4096 * 128, 4096, bx * 128,
                  nullptr, nullptr, 0);
    }
    gridbar();
    {   // LSTM2 (c_prev = 0) -> h2 fp32 + splits
        float vi[4] = {0,0,0,0}, vg[4] = {0,0,0,0}, vo[4] = {0,0,0,0};
        for (int s2 = 0; s2 < 4; s2++) {
            const float* pb = g_part + (size_t)s2 * 4096 * 128
                                     + (size_t)eb * 4096;
            float4 a = ldcg4(pb + ec);
            float4 c = ldcg4(pb + 2048 + ec);
            float4 d = ldcg4(pb + 3072 + ec);
            vi[0]+=a.x; vi[1]+=a.y; vi[2]+=a.z; vi[3]+=a.w;
            vg[0]+=c.x; vg[1]+=c.y; vg[2]+=c.z; vg[3]+=c.w;
            vo[0]+=d.x; vo[1]+=d.y; vo[2]+=d.z; vo[3]+=d.w;
        }
        float hv[4];
        #pragma unroll
        for (int j = 0; j < 4; j++) {
            int hg = ec + j;
            float i_ = vi[j] + bih2[hg]        + bhh2[hg];
            float g_ = vg[j] + bih2[2048 + hg] + bhh2[2048 + hg];
            float o_ = vo[j] + bih2[3072 + hg] + bhh2[3072 + hg];
            float c  = sigf(i_) * tanhf(g_);
            hv[j] = sigf(o_) * tanhf(c);
        }
        size_t o = (size_t)eb * Hq + ec;
        *(float4*)&g_h2[o] = make_float4(hv[0], hv[1], hv[2], hv[3]);
        store_split(g_h2h, g_h2l, o, hv[0], hv[1], hv[2], hv[3]);
    }
    gridbar();

    // ---- P8: fc (h2 @ fcW^T + fcb) -> rnn ----
    {
        int bx = cta >> 4, ks = cta & 15;
        gemm_tile(sb, g_h2h, g_h2l, ks * 64, fcW, Hq, bx * 128, ks * 64, 1,
                  g_part + (size_t)ks * Hq * 128, Hq, bx * 128,
                  nullptr, nullptr, 0);
    }
    gridbar();
    {
        float v0 = 0.f, v1 = 0.f, v2 = 0.f, v3 = 0.f;
        for (int s2 = 0; s2 < 16; s2++) {
            float4 p = ldcg4(g_part + (size_t)s2 * Hq * 128
                                    + (size_t)eb * Hq + ec);
            v0 += p.x; v1 += p.y; v2 += p.z; v3 += p.w;
        }
        float4 bv = *(const float4*)(fcb + ec);
        v0 += bv.x; v1 += bv.y; v2 += bv.z; v3 += bv.w;
        size_t o = (size_t)eb * Hq + ec;
        *(float4*)&g_rnn[o] = make_float4(v0, v1, v2, v3);
        store_split(g_rnh, g_rnl, o, v0, v1, v2, v3);
    }
    gridbar();

    // ---- P9: fused Luong attention (CTA = batch), ctx splits ----
    {
        const int b = cta, w = tid >> 5, lane = tid & 31;
        float* sacc = (float*)smem;            // 8 x 1024 floats (32 KB)
        __shared__ float ssm[8], ssl[8];

        float4 q[8];
        #pragma unroll
        for (int i = 0; i < 8; i++)
            q[i] = ldcg4(g_rnn + (size_t)b * Hq + (i * 32 + lane) * 4);

        float m = -1e30f, l = 0.f;
        float4 acc[8];
        #pragma unroll
        for (int i = 0; i < 8; i++) acc[i] = make_float4(0.f, 0.f, 0.f, 0.f);

        float4 ev[8], evn[8];
        {
            const float4* e = (const float4*)(enc + ((size_t)w * Bq + b) * Hq);
            #pragma unroll
            for (int i = 0; i < 8; i++) ev[i] = e[i * 32 + lane];
        }
        for (int s = w; s < Sq; s += 8) {
            int sn = s + 8;
            if (sn < Sq) {
                const float4* e = (const float4*)(enc + ((size_t)sn * Bq + b) * Hq);
                #pragma unroll
                for (int i = 0; i < 8; i++) evn[i] = e[i * 32 + lane];
            }
            float dot = 0.f;
            #pragma unroll
            for (int i = 0; i < 8; i++)
                dot += q[i].x * ev[i].x + q[i].y * ev[i].y
                     + q[i].z * ev[i].z + q[i].w * ev[i].w;
            #pragma unroll
            for (int o = 16; o > 0; o >>= 1)
                dot += __shfl_xor_sync(0xffffffffu, dot, o);
            float mn   = fmaxf(m, dot);
            float corr = expf(m - mn);
            float p    = expf(dot - mn);
            l = l * corr + p;
            #pragma unroll
            for (int i = 0; i < 8; i++) {
                acc[i].x = acc[i].x * corr + p * ev[i].x;
                acc[i].y = acc[i].y * corr + p * ev[i].y;
                acc[i].z = acc[i].z * corr + p * ev[i].z;
                acc[i].w = acc[i].w * corr + p * ev[i].w;
            }
            m = mn;
            #pragma unroll
            for (int i = 0; i < 8; i++) ev[i] = evn[i];
        }
        __syncthreads();   // smem handoff from prior GEMM use
        #pragma unroll
        for (int i = 0; i < 8; i++)
            ((float4*)(sacc + w * Hq))[i * 32 + lane] = acc[i];
        if (lane == 0) { ssm[w] = m; ssl[w] = l; }
        __syncthreads();

        float M = -1e30f;
        #pragma unroll
        for (int ww = 0; ww < 8; ww++) M = fmaxf(M, ssm[ww]);
        float wexp[8], L = 0.f;
        #pragma unroll
        for (int ww = 0; ww < 8; ww++) {
            wexp[ww] = expf(ssm[ww] - M);
            L += ssl[ww] * wexp[ww];
        }
        float invL = 1.f / L;

        int hh0 = tid * 4;
        float cx[4] = {0.f, 0.f, 0.f, 0.f};
        #pragma unroll
        for (int ww = 0; ww < 8; ww++) {
            float4 s4 = *(float4*)(sacc + ww * Hq + hh0);
            cx[0] += s4.x * wexp[ww]; cx[1] += s4.y * wexp[ww];
            cx[2] += s4.z * wexp[ww]; cx[3] += s4.w * wexp[ww];
        }
        store_split(g_cxh, g_cxl, (size_t)b * Hq + hh0,
                    cx[0] * invL, cx[1] * invL, cx[2] * invL, cx[3] * invL);
        __syncthreads();   // protect sacc before next GEMM phase reuses smem
    }
    gridbar();

    // ---- P10: concat ([rnn|ctx] @ ccW^T) -> tanh -> cc splits ----
    {
        int half = cta >> 6, j = cta & 63;
        int bx = j >> 3, ks = j & 7;
        const uint16_t* Ah = half ? g_cxh : g_rnh;
        const uint16_t* Al = half ? g_cxl : g_rnl;
        gemm_tile(sb, Ah, Al, ks * 128, ccW, 2 * Hq, bx * 128,
                  half * 1024 + ks * 128, 2,
                  g_part + (size_t)(half * 8 + ks) * Hq * 128, Hq, bx * 128,
                  nullptr, nullptr, 0);
    }
    gridbar();
    {
        float v0 = 0.f, v1 = 0.f, v2 = 0.f, v3 = 0.f;
        for (int s2 = 0; s2 < 16; s2++) {
            float4 p = ldcg4(g_part + (size_t)s2 * Hq * 128
                                    + (size_t)eb * Hq + ec);
            v0 += p.x; v1 += p.y; v2 += p.z; v3 += p.w;
        }
        float4 bv = *(const float4*)(ccb + ec);
        store_split(g_cch, g_ccl, (size_t)eb * Hq + ec,
                    tanhf(v0 + bv.x), tanhf(v1 + bv.y),
                    tanhf(v2 + bv.z), tanhf(v3 + bv.w));
    }
    gridbar();

    // ---- P11: output projection (direct, 250 tiles over 128 CTAs) ----
    gemm_tile(sb, g_cch, g_ccl, 0, outW, Hq, cta * 128, 0, 16,
              nullptr, 0, cta * 128, outb, g_logits, Vq);
    if (cta + 128 < Vq / 128)
        gemm_tile(sb, g_cch, g_ccl, 0, outW, Hq, (cta + 128) * 128, 0, 16,
                  nullptr, 0, (cta + 128) * 128, outb, g_logits, Vq);
    gridbar();

    // ---- P12: softmax (CTA = batch) + hidden copy ----
    {
        const int b = cta;
        const float* row = g_logits + (size_t)b * Vq;
        __shared__ float srm[256], srl[256];

        float m = -1e30f, l = 0.f;
        for (int v = tid; v < Vq / 4; v += 256) {
            float4 x = ldcg4(row + v * 4);
            float mx = fmaxf(fmaxf(x.x, x.y), fmaxf(x.z, x.w));
            float mn = fmaxf(m, mx);
            l = l * expf(m - mn) + expf(x.x - mn) + expf(x.y - mn)
                                 + expf(x.z - mn) + expf(x.w - mn);
            m = mn;
        }
        srm[tid] = m; srl[tid] = l;
        __syncthreads();
        for (int st = 128; st > 0; st >>= 1) {
            if (tid < st) {
                float m2 = fmaxf(srm[tid], srm[tid + st]);
                srl[tid] = srl[tid] * expf(srm[tid] - m2)
                         + srl[tid + st] * expf(srm[tid + st] - m2);
                srm[tid] = m2;
            }
            __syncthreads();
        }
        float M = srm[0], inv = 1.f / srl[0];

        float* o = out + (size_t)b * Vq;
        for (int v = tid; v < Vq / 4; v += 256) {
            float4 x = ldcg4(row + v * 4);
            *(float4*)&o[v * 4] =
                make_float4(expf(x.x - M) * inv, expf(x.y - M) * inv,
                            expf(x.z - M) * inv, expf(x.w - M) * inv);
        }
        if (copy_hidden) {
            float4 hv = ldcg4(g_h2 + (size_t)b * Hq + tid * 4);
            *(float4*)&out[(size_t)Bq * Vq + (size_t)b * Hq + tid * 4] = hv;
        }
    }
}

// ------------------------------- launch ------------------------------------
extern "C" void kernel_launch(void* const* d_in, const int* in_sizes, int n_in,
                              void* d_out, int out_size)
{
    const int*   step  = (const int*)  d_in[0];
    const float* enc   = (const float*)d_in[1];
    const float* h1    = (const float*)d_in[2];
    const float* c1    = (const float*)d_in[3];
    const float* emb   = (const float*)d_in[4];
    const float* mog1W = (const float*)d_in[5];
    const float* mog1b = (const float*)d_in[6];
    const float* Wih1  = (const float*)d_in[7];
    const float* Whh1  = (const float*)d_in[8];
    const float* bih1  = (const float*)d_in[9];
    const float* bhh1  = (const float*)d_in[10];
    const float* mog2b = (const float*)d_in[12];
    const float* Wih2  = (const float*)d_in[13];
    const float* bih2  = (const float*)d_in[15];
    const float* bhh2  = (const float*)d_in[16];
    const float* fcW   = (const float*)d_in[17];
    const float* fcb   = (const float*)d_in[18];
    const float* ccW   = (const float*)d_in[19];
    const float* ccb   = (const float*)d_in[20];
    const float* outW  = (const float*)d_in[21];
    const float* outb  = (const float*)d_in[22];
    float* out = (float*)d_out;

    cudaFuncSetAttribute(mega, cudaFuncAttributeMaxDynamicSharedMemorySize,
                         SMEM_BYTES);
    int copy_hidden = (out_size >= Bq * Vq + Bq * Hq) ? 1 : 0;

    mega<<<NB, 256, SMEM_BYTES>>>(step, enc, h1, c1, emb,
                                  mog1W, mog1b, Wih1, Whh1, bih1, bhh1,
                                  mog2b, Wih2, bih2, bhh2,
                                  fcW, fcb, ccW, ccb, outW, outb,
                                  out, copy_hidden);
}

// round 13
// speedup vs baseline: 2.9269x; 1.1980x over previous
#include <cuda_runtime.h>
#include <cuda_bf16.h>
#include <cstdint>
#include <cstddef>

// ---------------------------------------------------------------------------
// LuongAttnDecoderMogLSTM  (B=128, H=1024, S=512, V=32000, MOG=5)
// Round 12: persistent mega-kernel, 512 threads/CTA (16 warps) for 2x
// latency hiding. HMMA bf16x3 GEMM phases, grid-parallel epilogues,
// smem-resident q in attention.
// ---------------------------------------------------------------------------

#define Bq 128
#define Hq 1024
#define Sq 512
#define Vq 32000
#define NB 128          // persistent grid size (1 CTA/SM, all resident)
#define NT 512          // threads per CTA

static __device__ float    g_x  [Bq*Hq];
static __device__ uint16_t g_xh [Bq*Hq], g_xl [Bq*Hq];
static __device__ float    g_h  [Bq*Hq];
static __device__ uint16_t g_hh [Bq*Hq], g_hl [Bq*Hq];
static __device__ uint16_t g_x2h[Bq*Hq], g_x2l[Bq*Hq];
static __device__ float    g_h2 [Bq*Hq];
static __device__ uint16_t g_h2h[Bq*Hq], g_h2l[Bq*Hq];
static __device__ float    g_rnn[Bq*Hq];
static __device__ uint16_t g_rnh[Bq*Hq], g_rnl[Bq*Hq];
static __device__ uint16_t g_cxh[Bq*Hq], g_cxl[Bq*Hq];
static __device__ uint16_t g_cch[Bq*Hq], g_ccl[Bq*Hq];
static __device__ float    g_part[8*4096*Bq];        // split-K partials
static __device__ float    g_logits[(size_t)Bq*Vq];
static __device__ int      g_barc, g_barg;           // grid barrier state

__device__ __forceinline__ float sigf(float x) { return 1.f / (1.f + expf(-x)); }

__device__ __forceinline__ uint32_t smem_u32(const void* p) {
    uint32_t a;
    asm("{ .reg .u64 t; cvta.to.shared.u64 t, %1; cvt.u32.u64 %0, t; }"
        : "=r"(a) : "l"(p));
    return a;
}

// L1-bypassing loads (persistent kernel: buffers written by other SMs)
__device__ __forceinline__ float2 ldcg2(const float* p) {
    float2 v;
    asm volatile("ld.global.cg.v2.f32 {%0,%1}, [%2];"
                 : "=f"(v.x), "=f"(v.y) : "l"(p));
    return v;
}
__device__ __forceinline__ float4 ldcg4(const float* p) {
    float4 v;
    asm volatile("ld.global.cg.v4.f32 {%0,%1,%2,%3}, [%4];"
                 : "=f"(v.x), "=f"(v.y), "=f"(v.z), "=f"(v.w) : "l"(p));
    return v;
}
__device__ __forceinline__ uint4 ldcg4u(const void* p) {
    uint4 v;
    asm volatile("ld.global.cg.v4.b32 {%0,%1,%2,%3}, [%4];"
                 : "=r"(v.x), "=r"(v.y), "=r"(v.z), "=r"(v.w) : "l"(p));
    return v;
}

// grid-wide barrier (all NB CTAs co-resident; generation counter sense)
__device__ __forceinline__ void gridbar() {
    __syncthreads();
    if (threadIdx.x == 0) {
        __threadfence();
        int gen = *(volatile int*)&g_barg;
        if (atomicAdd(&g_barc, 1) == NB - 1) {
            g_barc = 0;
            __threadfence();
            *(volatile int*)&g_barg = gen + 1;
        } else {
            while (*(volatile int*)&g_barg == gen) { }
        }
        __threadfence();
    }
    __syncthreads();
}

#define STS128(addr, a, b, c, d) \
    asm volatile("st.shared.v4.b32 [%0], {%1, %2, %3, %4};" \
                 :: "r"(addr), "r"(a), "r"(b), "r"(c), "r"(d) : "memory")

__device__ __forceinline__ void ldsm4(uint32_t a, uint32_t& r0, uint32_t& r1,
                                      uint32_t& r2, uint32_t& r3) {
    asm volatile("ldmatrix.sync.aligned.m8n8.x4.shared.b16 {%0,%1,%2,%3}, [%4];"
                 : "=r"(r0), "=r"(r1), "=r"(r2), "=r"(r3) : "r"(a));
}

// fp32 pair -> packed bf16 hi (truncated) + lo (rounded residual)
__device__ __forceinline__ void cvt_pair(float f0, float f1,
                                         uint32_t& hp, uint32_t& lp) {
    uint32_t u0 = __float_as_uint(f0), u1 = __float_as_uint(f1);
    asm("prmt.b32 %0, %1, %2, 0x7632;" : "=r"(hp) : "r"(u0), "r"(u1));
    float l0 = f0 - __uint_as_float(u0 & 0xFFFF0000u);
    float l1 = f1 - __uint_as_float(u1 & 0xFFFF0000u);
    asm("cvt.rn.bf16x2.f32 %0, %1, %2;" : "=r"(lp) : "f"(l1), "f"(l0));
}

// store 2 consecutive activation values as splits (o 2-aligned)
__device__ __forceinline__ void store_split2(uint16_t* th, uint16_t* tl,
                                             size_t o, float a, float b) {
    uint32_t hp, lp;
    cvt_pair(a, b, hp, lp);
    *(uint32_t*)&th[o] = hp;
    *(uint32_t*)&tl[o] = lp;
}

// 16B-aligned fragment row address in a SW128 128x64-bf16 smem tile
__device__ __forceinline__ uint32_t fragaddr(uint32_t base, int row, int bo) {
    return base + (uint32_t)row * 128u
                + (uint32_t)((((bo >> 4) ^ (row & 7)) << 4));
}

#define MMA_BF16(d, a, b0_, b1_) \
    asm volatile("mma.sync.aligned.m16n8k16.row.col.f32.bf16.bf16.f32 " \
        "{%0,%1,%2,%3}, {%4,%5,%6,%7}, {%8,%9}, {%0,%1,%2,%3};" \
        : "+f"((d)[0]), "+f"((d)[1]), "+f"((d)[2]), "+f"((d)[3]) \
        : "r"((a)[0]), "r"((a)[1]), "r"((a)[2]), "r"((a)[3]), \
          "r"(b0_), "r"(b1_))

#define GBUF 65536u
#define SMEM_BYTES 131072

// ============================ gemm_tile ====================================
// One 128(b) x 128(n) x (64*T)(k) tile, bf16x3, 16 warps (32x32 warp tiles).
__device__ __noinline__ void gemm_tile(uint32_t sb,
    const uint16_t* __restrict__ Ah, const uint16_t* __restrict__ Al, int akoff,
    const float* __restrict__ W, int ldw, int wrow0, int wkoff, int T,
    float* __restrict__ Pout, int PNp, int n0,
    const float* __restrict__ bias, float* __restrict__ Dout, int Nd)
{
    const int tid = threadIdx.x, lane = tid & 31, wid = tid >> 5;
    const int r = tid >> 2, c0 = (tid & 3) << 4;
    const uint16_t* ahp = Ah + (size_t)r * Hq + akoff + c0;
    const uint16_t* alp = Al + (size_t)r * Hq + akoff + c0;
    const float*    wp  = W  + (size_t)(wrow0 + r) * ldw + wkoff + c0;

    const int wm = (wid & 3) * 32, wn = (wid >> 2) * 32;
    const int lr = lane & 15, lk = (lane >> 4) << 4;

    float acc[2][4][4];
    #pragma unroll
    for (int mf = 0; mf < 2; mf++)
        #pragma unroll
        for (int nf = 0; nf < 4; nf++)
            #pragma unroll
            for (int j = 0; j < 4; j++) acc[mf][nf][j] = 0.f;

    uint4 pa[2], pb[2]; float4 fw[4];
    #pragma unroll
    for (int g = 0; g < 2; g++) {
        pa[g] = ldcg4u(ahp + g * 8);
        pb[g] = ldcg4u(alp + g * 8);
    }
    #pragma unroll
    for (int i = 0; i < 4; i++) fw[i] = *(const float4*)(wp + i * 4);

    for (int t = 0; t < T; t++) {
        const uint32_t base = sb + (uint32_t)(t & 1) * GBUF;
        #pragma unroll
        for (int g = 0; g < 2; g++) {
            uint32_t byte = (uint32_t)r * 128u + (uint32_t)(c0 + g * 8) * 2u;
            uint32_t sw = byte ^ ((byte >> 3) & 0x70u);
            STS128(base + sw,          pa[g].x, pa[g].y, pa[g].z, pa[g].w);
            STS128(base + 16384u + sw, pb[g].x, pb[g].y, pb[g].z, pb[g].w);
            float4 f0 = fw[2 * g], f1 = fw[2 * g + 1];
            uint32_t h0, h1, l0, l1;
            cvt_pair(f0.x, f0.y, h0, l0);
            cvt_pair(f0.z, f0.w, h1, l1);
            uint32_t h2, h3, l2, l3;
            cvt_pair(f1.x, f1.y, h2, l2);
            cvt_pair(f1.z, f1.w, h3, l3);
            STS128(base + 32768u + sw, h0, h1, h2, h3);
            STS128(base + 49152u + sw, l0, l1, l2, l3);
        }
        __syncthreads();

        if (t + 1 < T) {
            #pragma unroll
            for (int g = 0; g < 2; g++) {
                pa[g] = ldcg4u(ahp + (t + 1) * 64 + g * 8);
                pb[g] = ldcg4u(alp + (t + 1) * 64 + g * 8);
            }
            #pragma unroll
            for (int i = 0; i < 4; i++)
                fw[i] = *(const float4*)(wp + (t + 1) * 64 + i * 4);
        }

        #pragma unroll
        for (int kf = 0; kf < 4; kf++) {
            const int bo = kf * 32 + lk;
            uint32_t ah4[2][4], al4[2][4];
            #pragma unroll
            for (int mf = 0; mf < 2; mf++) {
                uint32_t ad = fragaddr(base, wm + mf * 16 + lr, bo);
                ldsm4(ad,          ah4[mf][0], ah4[mf][1], ah4[mf][2], ah4[mf][3]);
                ldsm4(ad + 16384u, al4[mf][0], al4[mf][1], al4[mf][2], al4[mf][3]);
            }
            #pragma unroll
            for (int p = 0; p < 2; p++) {
                uint32_t bd = fragaddr(base + 32768u, wn + p * 16 + lr, bo);
                uint32_t bh[4], bl[4];
                ldsm4(bd,          bh[0], bh[1], bh[2], bh[3]);
                ldsm4(bd + 16384u, bl[0], bl[1], bl[2], bl[3]);
                #pragma unroll
                for (int q = 0; q < 2; q++) {
                    const int nf = 2 * p + q;
                    #pragma unroll
                    for (int mf = 0; mf < 2; mf++) {
                        MMA_BF16(acc[mf][nf], ah4[mf], bh[q], bh[q + 2]);
                        MMA_BF16(acc[mf][nf], al4[mf], bh[q], bh[q + 2]);
                        MMA_BF16(acc[mf][nf], ah4[mf], bl[q], bl[q + 2]);
                    }
                }
            }
        }
        __syncthreads();
    }

    if (Dout) {
        #pragma unroll
        for (int mf = 0; mf < 2; mf++) {
            int rr = wm + mf * 16 + (lane >> 2);
            #pragma unroll
            for (int nf = 0; nf < 4; nf++) {
                int nn = n0 + wn + nf * 8 + (lane & 3) * 2;
                float b0 = bias[nn], b1 = bias[nn + 1];
                *(float2*)&Dout[(size_t)rr * Nd + nn] =
                    make_float2(acc[mf][nf][0] + b0, acc[mf][nf][1] + b1);
                *(float2*)&Dout[(size_t)(rr + 8) * Nd + nn] =
                    make_float2(acc[mf][nf][2] + b0, acc[mf][nf][3] + b1);
            }
        }
    } else {
        #pragma unroll
        for (int mf = 0; mf < 2; mf++) {
            int rr = wm + mf * 16 + (lane >> 2);
            #pragma unroll
            for (int nf = 0; nf < 4; nf++) {
                int nn = n0 + wn + nf * 8 + (lane & 3) * 2;
                *(float2*)&Pout[(size_t)rr * PNp + nn] =
                    make_float2(acc[mf][nf][0], acc[mf][nf][1]);
                *(float2*)&Pout[(size_t)(rr + 8) * PNp + nn] =
                    make_float2(acc[mf][nf][2], acc[mf][nf][3]);
            }
        }
    }
}

// ============================ mega kernel ==================================
__global__ void __launch_bounds__(NT, 1)
mega(const int* __restrict__ step, const float* __restrict__ enc,
     const float* __restrict__ h1, const float* __restrict__ c1,
     const float* __restrict__ emb,
     const float* __restrict__ mog1W, const float* __restrict__ mog1b,
     const float* __restrict__ Wih1, const float* __restrict__ Whh1,
     const float* __restrict__ bih1, const float* __restrict__ bhh1,
     const float* __restrict__ mog2b, const float* __restrict__ Wih2,
     const float* __restrict__ bih2, const float* __restrict__ bhh2,
     const float* __restrict__ fcW, const float* __restrict__ fcb,
     const float* __restrict__ ccW, const float* __restrict__ ccb,
     const float* __restrict__ outW, const float* __restrict__ outb,
     float* __restrict__ out, int copy_hidden)
{
    extern __shared__ char smem[];
    const uint32_t sb = smem_u32(smem);
    const int cta = blockIdx.x, tid = threadIdx.x;
    const int gid = cta * NT + tid;        // 0..65535
    const int eb  = gid >> 9;              // batch for elementwise phases
    const int ec  = (gid & 511) * 2;       // 2 consecutive cols

    // ---- P0: prep (embed + state copy, with splits) ----
    {
        int s = step[eb];
        float2 xv = *(const float2*)(emb + (size_t)s * Hq + ec);
        float2 hv = *(const float2*)(h1 + (size_t)eb * Hq + ec);
        size_t o = (size_t)eb * Hq + ec;
        *(float2*)&g_x[o] = xv;
        *(float2*)&g_h[o] = hv;
        store_split2(g_xh, g_xl, o, xv.x, xv.y);
        store_split2(g_hh, g_hl, o, hv.x, hv.y);
    }
    gridbar();

    // ---- P1-P5: layer-1 mogrifier ----
    #pragma unroll 1
    for (int i = 0; i < 5; i++) {
        const uint16_t* Ah = (i & 1) ? g_xh : g_hh;
        const uint16_t* Al = (i & 1) ? g_xl : g_hl;
        int bx = cta >> 4, ks = cta & 15;
        gemm_tile(sb, Ah, Al, ks * 64, mog1W + (size_t)i * Hq * Hq, Hq,
                  bx * 128, ks * 64, 1,
                  g_part + (size_t)ks * Hq * 128, Hq, bx * 128,
                  nullptr, nullptr, 0);
        gridbar();
        {
            float v0 = 0.f, v1 = 0.f;
            for (int s2 = 0; s2 < 16; s2++) {
                float2 p = ldcg2(g_part + (size_t)s2 * Hq * 128
                                        + (size_t)eb * Hq + ec);
                v0 += p.x; v1 += p.y;
            }
            float2 bv = *(const float2*)(mog1b + i * Hq + ec);
            float*    tf = (i & 1) ? g_h  : g_x;
            uint16_t* th = (i & 1) ? g_hh : g_xh;
            uint16_t* tl = (i & 1) ? g_hl : g_xl;
            size_t o = (size_t)eb * Hq + ec;
            float2 xo = ldcg2(tf + o);
            float n0 = xo.x * 2.f * sigf(v0 + bv.x);
            float n1 = xo.y * 2.f * sigf(v1 + bv.y);
            *(float2*)&tf[o] = make_float2(n0, n1);
            store_split2(th, tl, o, n0, n1);
        }
        gridbar();
    }

    // ---- P6: layer-1 gates (x@Wih1 + h@Whh1), 2 jobs/CTA ----
    {
        int bx = cta >> 2, ks = cta & 3;
        gemm_tile(sb, g_xh, g_xl, ks * 256, Wih1, Hq, bx * 128, ks * 256, 4,
                  g_part + (size_t)ks * 4096 * 128, 4096, bx * 128,
                  nullptr, nullptr, 0);
        gemm_tile(sb, g_hh, g_hl, ks * 256, Whh1, Hq, bx * 128, ks * 256, 4,
                  g_part + (size_t)(4 + ks) * 4096 * 128, 4096, bx * 128,
                  nullptr, nullptr, 0);
    }
    gridbar();
    {   // LSTM1 + layer-2 mogrifier (bias-only) -> x2 splits
        float vi[2] = {0,0}, vf[2] = {0,0}, vg[2] = {0,0}, vo[2] = {0,0};
        for (int s2 = 0; s2 < 8; s2++) {
            const float* pb = g_part + (size_t)s2 * 4096 * 128
                                     + (size_t)eb * 4096;
            float2 a = ldcg2(pb + ec);
            float2 b = ldcg2(pb + 1024 + ec);
            float2 c = ldcg2(pb + 2048 + ec);
            float2 d = ldcg2(pb + 3072 + ec);
            vi[0]+=a.x; vi[1]+=a.y; vf[0]+=b.x; vf[1]+=b.y;
            vg[0]+=c.x; vg[1]+=c.y; vo[0]+=d.x; vo[1]+=d.y;
        }
        float2 cv = *(const float2*)(c1 + (size_t)eb * Hq + ec);
        float cvv[2] = {cv.x, cv.y};
        float x2v[2];
        #pragma unroll
        for (int j = 0; j < 2; j++) {
            int hg = ec + j;
            float i_ = vi[j] + bih1[hg]        + bhh1[hg];
            float f_ = vf[j] + bih1[1024 + hg] + bhh1[1024 + hg];
            float g_ = vg[j] + bih1[2048 + hg] + bhh1[2048 + hg];
            float o_ = vo[j] + bih1[3072 + hg] + bhh1[3072 + hg];
            float c  = sigf(f_) * cvv[j] + sigf(i_) * tanhf(g_);
            float hv = sigf(o_) * tanhf(c);
            float sc = 8.f * sigf(mog2b[hg]) * sigf(mog2b[2048 + hg])
                           * sigf(mog2b[4096 + hg]);
            x2v[j] = hv * sc;
        }
        store_split2(g_x2h, g_x2l, (size_t)eb * Hq + ec, x2v[0], x2v[1]);
    }
    gridbar();

    // ---- P7: layer-2 gates (x2@Wih2) ----
    {
        int bx = cta >> 2, ks = cta & 3;
        gemm_tile(sb, g_x2h, g_x2l, ks * 256, Wih2, Hq, bx * 128, ks * 256, 4,
                  g_part + (size_t)ks * 4096 * 128, 4096, bx * 128,
                  nullptr, nullptr, 0);
    }
    gridbar();
    {   // LSTM2 (c_prev = 0) -> h2 fp32 + splits
        float vi[2] = {0,0}, vg[2] = {0,0}, vo[2] = {0,0};
        for (int s2 = 0; s2 < 4; s2++) {
            const float* pb = g_part + (size_t)s2 * 4096 * 128
                                     + (size_t)eb * 4096;
            float2 a = ldcg2(pb + ec);
            float2 c = ldcg2(pb + 2048 + ec);
            float2 d = ldcg2(pb + 3072 + ec);
            vi[0]+=a.x; vi[1]+=a.y; vg[0]+=c.x; vg[1]+=c.y;
            vo[0]+=d.x; vo[1]+=d.y;
        }
        float hv[2];
        #pragma unroll
        for (int j = 0; j < 2; j++) {
            int hg = ec + j;
            float i_ = vi[j] + bih2[hg]        + bhh2[hg];
            float g_ = vg[j] + bih2[2048 + hg] + bhh2[2048 + hg];
            float o_ = vo[j] + bih2[3072 + hg] + bhh2[3072 + hg];
            float c  = sigf(i_) * tanhf(g_);
            hv[j] = sigf(o_) * tanhf(c);
        }
        size_t o = (size_t)eb * Hq + ec;
        *(float2*)&g_h2[o] = make_float2(hv[0], hv[1]);
        store_split2(g_h2h, g_h2l, o, hv[0], hv[1]);
    }
    gridbar();

    // ---- P8: fc (h2 @ fcW^T + fcb) -> rnn ----
    {
        int bx = cta >> 4, ks = cta & 15;
        gemm_tile(sb, g_h2h, g_h2l, ks * 64, fcW, Hq, bx * 128, ks * 64, 1,
                  g_part + (size_t)ks * Hq * 128, Hq, bx * 128,
                  nullptr, nullptr, 0);
    }
    gridbar();
    {
        float v0 = 0.f, v1 = 0.f;
        for (int s2 = 0; s2 < 16; s2++) {
            float2 p = ldcg2(g_part + (size_t)s2 * Hq * 128
                                    + (size_t)eb * Hq + ec);
            v0 += p.x; v1 += p.y;
        }
        float2 bv = *(const float2*)(fcb + ec);
        v0 += bv.x; v1 += bv.y;
        size_t o = (size_t)eb * Hq + ec;
        *(float2*)&g_rnn[o] = make_float2(v0, v1);
        store_split2(g_rnh, g_rnl, o, v0, v1);
    }
    gridbar();

    // ---- P9: fused Luong attention (CTA = batch, 16 warps, q in smem) ----
    {
        const int b = cta, w = tid >> 5, lane = tid & 31;
        float* sq   = (float*)smem;                 // 1024 floats (4 KB)
        float* sacc = (float*)(smem + 8192);        // 16 x 1024 (64 KB)
        __shared__ float ssm[16], ssl[16];

        {
            float2 qv = ldcg2(g_rnn + (size_t)b * Hq + tid * 2);
            *(float2*)&sq[tid * 2] = qv;
        }
        __syncthreads();

        float m = -1e30f, l = 0.f;
        float4 acc[8];
        #pragma unroll
        for (int i = 0; i < 8; i++) acc[i] = make_float4(0.f, 0.f, 0.f, 0.f);

        for (int s = w; s < Sq; s += 16) {
            const float4* e = (const float4*)(enc + ((size_t)s * Bq + b) * Hq);
            float4 ev[8];
            float dot = 0.f;
            #pragma unroll
            for (int i = 0; i < 8; i++) {
                ev[i] = e[i * 32 + lane];
                float4 qq = *(float4*)&sq[(i * 32 + lane) * 4];
                dot += qq.x * ev[i].x + qq.y * ev[i].y
                     + qq.z * ev[i].z + qq.w * ev[i].w;
            }
            #pragma unroll
            for (int o = 16; o > 0; o >>= 1)
                dot += __shfl_xor_sync(0xffffffffu, dot, o);
            float mn   = fmaxf(m, dot);
            float corr = expf(m - mn);
            float p    = expf(dot - mn);
            l = l * corr + p;
            #pragma unroll
            for (int i = 0; i < 8; i++) {
                acc[i].x = acc[i].x * corr + p * ev[i].x;
                acc[i].y = acc[i].y * corr + p * ev[i].y;
                acc[i].z = acc[i].z * corr + p * ev[i].z;
                acc[i].w = acc[i].w * corr + p * ev[i].w;
            }
            m = mn;
        }
        __syncthreads();
        #pragma unroll
        for (int i = 0; i < 8; i++)
            ((float4*)(sacc + w * Hq))[i * 32 + lane] = acc[i];
        if (lane == 0) { ssm[w] = m; ssl[w] = l; }
        __syncthreads();

        float M = -1e30f;
        #pragma unroll
        for (int ww = 0; ww < 16; ww++) M = fmaxf(M, ssm[ww]);
        float L = 0.f;
        #pragma unroll
        for (int ww = 0; ww < 16; ww++) L += ssl[ww] * expf(ssm[ww] - M);
        float invL = 1.f / L;

        int hh0 = tid * 2;
        float c0 = 0.f, c1v = 0.f;
        #pragma unroll
        for (int ww = 0; ww < 16; ww++) {
            float wexp = expf(ssm[ww] - M);
            float2 s2 = *(float2*)&sacc[ww * Hq + hh0];
            c0 += s2.x * wexp; c1v += s2.y * wexp;
        }
        store_split2(g_cxh, g_cxl, (size_t)b * Hq + hh0,
                     c0 * invL, c1v * invL);
        __syncthreads();
    }
    gridbar();

    // ---- P10: concat ([rnn|ctx] @ ccW^T) -> tanh -> cc splits ----
    {
        int half = cta >> 6, j = cta & 63;
        int bx = j >> 3, ks = j & 7;
        const uint16_t* Ah = half ? g_cxh : g_rnh;
        const uint16_t* Al = half ? g_cxl : g_rnl;
        gemm_tile(sb, Ah, Al, ks * 128, ccW, 2 * Hq, bx * 128,
                  half * 1024 + ks * 128, 2,
                  g_part + (size_t)(half * 8 + ks) * Hq * 128, Hq, bx * 128,
                  nullptr, nullptr, 0);
    }
    gridbar();
    {
        float v0 = 0.f, v1 = 0.f;
        for (int s2 = 0; s2 < 16; s2++) {
            float2 p = ldcg2(g_part + (size_t)s2 * Hq * 128
                                    + (size_t)eb * Hq + ec);
            v0 += p.x; v1 += p.y;
        }
        float2 bv = *(const float2*)(ccb + ec);
        store_split2(g_cch, g_ccl, (size_t)eb * Hq + ec,
                     tanhf(v0 + bv.x), tanhf(v1 + bv.y));
    }
    gridbar();

    // ---- P11: output projection (direct, 250 tiles over 128 CTAs) ----
    gemm_tile(sb, g_cch, g_ccl, 0, outW, Hq, cta * 128, 0, 16,
              nullptr, 0, cta * 128, outb, g_logits, Vq);
    if (cta + 128 < Vq / 128)
        gemm_tile(sb, g_cch, g_ccl, 0, outW, Hq, (cta + 128) * 128, 0, 16,
                  nullptr, 0, (cta + 128) * 128, outb, g_logits, Vq);
    gridbar();

    // ---- P12: softmax (CTA = batch) + hidden copy ----
    {
        const int b = cta;
        const float* row = g_logits + (size_t)b * Vq;
        __shared__ float srm[NT], srl[NT];

        float m = -1e30f, l = 0.f;
        for (int v = tid; v < Vq / 4; v += NT) {
            float4 x = ldcg4(row + v * 4);
            float mx = fmaxf(fmaxf(x.x, x.y), fmaxf(x.z, x.w));
            float mn = fmaxf(m, mx);
            l = l * expf(m - mn) + expf(x.x - mn) + expf(x.y - mn)
                                 + expf(x.z - mn) + expf(x.w - mn);
            m = mn;
        }
        srm[tid] = m; srl[tid] = l;
        __syncthreads();
        for (int st = NT / 2; st > 0; st >>= 1) {
            if (tid < st) {
                float m2 = fmaxf(srm[tid], srm[tid + st]);
                srl[tid] = srl[tid] * expf(srm[tid] - m2)
                         + srl[tid + st] * expf(srm[tid + st] - m2);
                srm[tid] = m2;
            }
            __syncthreads();
        }
        float M = srm[0], inv = 1.f / srl[0];

        float* o = out + (size_t)b * Vq;
        for (int v = tid; v < Vq / 4; v += NT) {
            float4 x = ldcg4(row + v * 4);
            *(float4*)&o[v * 4] =
                make_float4(expf(x.x - M) * inv, expf(x.y - M) * inv,
                            expf(x.z - M) * inv, expf(x.w - M) * inv);
        }
        if (copy_hidden) {
            float2 hv = ldcg2(g_h2 + (size_t)b * Hq + tid * 2);
            *(float2*)&out[(size_t)Bq * Vq + (size_t)b * Hq + tid * 2] = hv;
        }
    }
}

// ------------------------------- launch ------------------------------------
extern "C" void kernel_launch(void* const* d_in, const int* in_sizes, int n_in,
                              void* d_out, int out_size)
{
    const int*   step  = (const int*)  d_in[0];
    const float* enc   = (const float*)d_in[1];
    const float* h1    = (const float*)d_in[2];
    const float* c1    = (const float*)d_in[3];
    const float* emb   = (const float*)d_in[4];
    const float* mog1W = (const float*)d_in[5];
    const float* mog1b = (const float*)d_in[6];
    const float* Wih1  = (const float*)d_in[7];
    const float* Whh1  = (const float*)d_in[8];
    const float* bih1  = (const float*)d_in[9];
    const float* bhh1  = (const float*)d_in[10];
    const float* mog2b = (const float*)d_in[12];
    const float* Wih2  = (const float*)d_in[13];
    const float* bih2  = (const float*)d_in[15];
    const float* bhh2  = (const float*)d_in[16];
    const float* fcW   = (const float*)d_in[17];
    const float* fcb   = (const float*)d_in[18];
    const float* ccW   = (const float*)d_in[19];
    const float* ccb   = (const float*)d_in[20];
    const float* outW  = (const float*)d_in[21];
    const float* outb  = (const float*)d_in[22];
    float* out = (float*)d_out;

    cudaFuncSetAttribute(mega, cudaFuncAttributeMaxDynamicSharedMemorySize,
                         SMEM_BYTES);
    int copy_hidden = (out_size >= Bq * Vq + Bq * Hq) ? 1 : 0;

    mega<<<NB, NT, SMEM_BYTES>>>(step, enc, h1, c1, emb,
                                 mog1W, mog1b, Wih1, Whh1, bih1, bhh1,
                                 mog2b, Wih2, bih2, bhh2,
                                 fcW, fcb, ccW, ccb, outW, outb,
                                 out, copy_hidden);
}